// round 8
// baseline (speedup 1.0000x reference)
#include <cuda_runtime.h>
#include <cuda_bf16.h>
#include <cstdint>

#define NM     512
#define BATCH  32
#define DIMK   64
#define BIGF   1e30f
#define SENTU  0x7fc00000u

// Front-major packed D (pre-scaled by log2 e): g_Df[b][s][m][k],
// s = i+j (front), m = i>>7, k = i&127. Unwritten slots are zero (BSS).
// s rows: 1056 allocated (1023 valid + prefetch pad).
#define SROWS 1056
__device__ __align__(16) float g_Df[(size_t)BATCH * SROWS * 512];

#define STEPS 1024
#define SLOTS 1024     // one write-once float4 slot per warp per step

__device__ __forceinline__ float ex2f(float x) {
    float r; asm("ex2.approx.f32 %0, %1;" : "=f"(r) : "f"(x)); return r;
}
__device__ __forceinline__ float lg2f(float x) {
    float r; asm("lg2.approx.f32 %0, %1;" : "=f"(r) : "f"(x)); return r;
}
// smem spin (raw backward branch): wait until *p != sentinel.
__device__ __forceinline__ void spin_lds(const float* p) {
    unsigned a = (unsigned)__cvta_generic_to_shared(p);
    unsigned v;
    asm volatile(
        "{\n\t.reg .pred sp;\n"
        "SPINS%=:\n\t"
        "ld.volatile.shared.b32 %0, [%1];\n\t"
        "setp.eq.u32 sp, %0, 0x7fc00000;\n\t"
        "@sp bra SPINS%=;\n\t}"
        : "=r"(v) : "r"(a) : "memory");
}
__device__ __forceinline__ void sts_v4(float* p, float a, float b, float c, float d) {
    unsigned ad = (unsigned)__cvta_generic_to_shared(p);
    asm volatile("st.volatile.shared.v4.f32 [%0], {%1,%2,%3,%4};"
                 :: "r"(ad), "f"(a), "f"(b), "f"(c), "f"(d) : "memory");
}

// ---------------------------------------------------------------------------
// Kernel 1: pairwise sqdist * log2(e), packed into front-major g_Df.
// 64x64 tiles, 256 threads, 4x4 microtiles. stage aliases Xs.
// ---------------------------------------------------------------------------
__global__ void __launch_bounds__(256) pairdist_kernel(
    const float* __restrict__ X, const float* __restrict__ Y)
{
    __shared__ __align__(16) float Xs[64 * 68];   // reused as stage[jl*65+il]
    __shared__ __align__(16) float Ys[64 * 68];
    __shared__ __align__(16) float x2s[64];
    __shared__ __align__(16) float y2s[64];

    const int b  = blockIdx.z;
    const int i0 = blockIdx.x * 64;
    const int j0 = blockIdx.y * 64;
    const int tid = threadIdx.x;

    const float* Xb = X + ((size_t)b * NM + i0) * DIMK;
    const float* Yb = Y + ((size_t)b * NM + j0) * DIMK;

    for (int t = tid; t < 64 * 64; t += 256) {
        int r = t >> 6, k = t & 63;
        Xs[k * 68 + r] = Xb[r * DIMK + k];
        Ys[k * 68 + r] = Yb[r * DIMK + k];
    }
    __syncthreads();

    if (tid < 128) {
        int r = tid & 63;
        const float* S = (tid < 64) ? Xs : Ys;
        float acc = 0.f;
        #pragma unroll 8
        for (int k = 0; k < 64; ++k) { float v = S[k * 68 + r]; acc += v * v; }
        if (tid < 64) x2s[r] = acc; else y2s[r] = acc;
    }
    __syncthreads();

    const int tx = tid & 15, ty = tid >> 4;
    float acc[4][4];
    #pragma unroll
    for (int a = 0; a < 4; ++a)
        #pragma unroll
        for (int c = 0; c < 4; ++c) acc[a][c] = 0.f;

    #pragma unroll 8
    for (int k = 0; k < 64; ++k) {
        float4 xv = *(const float4*)&Xs[k * 68 + 4 * tx];
        float4 yv = *(const float4*)&Ys[k * 68 + 4 * ty];
        float xr[4] = {xv.x, xv.y, xv.z, xv.w};
        float yr[4] = {yv.x, yv.y, yv.z, yv.w};
        #pragma unroll
        for (int jj = 0; jj < 4; ++jj)
            #pragma unroll
            for (int ii = 0; ii < 4; ++ii)
                acc[jj][ii] += yr[jj] * xr[ii];
    }

    const float L2E = 1.4426950408889634f;
    float4 x2v = *(const float4*)&x2s[4 * tx];
    float xr2[4] = {x2v.x, x2v.y, x2v.z, x2v.w};
    float outv[4][4];
    #pragma unroll
    for (int jj = 0; jj < 4; ++jj) {
        float y2 = y2s[4 * ty + jj];
        #pragma unroll
        for (int ii = 0; ii < 4; ++ii)
            outv[jj][ii] = (xr2[ii] + y2 - 2.f * acc[jj][ii]) * L2E;
    }
    __syncthreads();

    float* stage = Xs;
    #pragma unroll
    for (int jj = 0; jj < 4; ++jj)
        #pragma unroll
        for (int ii = 0; ii < 4; ++ii)
            stage[(4 * ty + jj) * 65 + 4 * tx + ii] = outv[jj][ii];
    __syncthreads();

    // Front-major writeout: tile diagonal sd -> front s=i0+j0+sd; elements
    // il in [lo,hi] contiguous at [s][m][k0+il] (fully coalesced runs).
    const int wk   = tid >> 5;
    const int lane = tid & 31;
    const int m    = i0 >> 7;
    const int k0   = i0 & 127;
    float* gout = g_Df + (size_t)b * SROWS * 512;
    for (int sd = wk; sd < 127; sd += 8) {
        int lo = sd > 63 ? sd - 63 : 0;
        int hi = sd < 63 ? sd : 63;
        float* dst = gout + (size_t)(i0 + j0 + sd) * 512 + m * 128 + k0;
        for (int il = lo + lane; il <= hi; il += 32)
            dst[il] = stage[(sd - il) * 65 + il];
    }
}

// ---------------------------------------------------------------------------
// Kernel 2: soft-DTW front sweep. 1 CTA/batch, 128 threads (4 warps).
// Lane tid owns rows i = tid + 128m (m=0..3). Step s computes the 4 cells
// of front t=s (independent -> MUFUs pipeline). up: shfl within warp; smem
// write-once float4 slots across warp boundaries (data-is-flag, no reuse).
// ---------------------------------------------------------------------------
__global__ void __launch_bounds__(128, 1) sdtw_kernel(float* __restrict__ out)
{
    extern __shared__ __align__(16) float slots[];   // [4][SLOTS][4]

    const int tid  = threadIdx.x;
    const int b    = blockIdx.x;
    const int w    = tid >> 5;
    const int lane = tid & 31;
    const bool is0  = (lane == 0);
    const bool is31 = (lane == 31);
    const bool w0   = (w == 0);

    // init sentinel word (.w) of every slot
    for (int t = tid; t < 4 * SLOTS; t += 128)
        slots[t * 4 + 3] = __uint_as_float(SENTU);
    __syncthreads();

    const float* gD = g_Df + (size_t)b * SROWS * 512 + tid;
    // prefetch ring: 8 steps x 4 groups
    float dring[8][4];
    #pragma unroll
    for (int p = 0; p < 8; ++p)
        #pragma unroll
        for (int mm = 0; mm < 4; ++mm)
            dring[p][mm] = gD[(size_t)p * 512 + mm * 128];
    const float* dp = gD + (size_t)8 * 512;

    float*       myslot  = slots + (size_t)w * SLOTS * 4;
    const float* prdslot = slots + (size_t)((w + 3) & 3) * SLOTS * 4;

    // state per group
    float v[4], diag[4], lo[4], hi[4];
    #pragma unroll
    for (int mm = 0; mm < 4; ++mm) {
        v[mm] = BIGF; diag[mm] = BIGF;
        lo[mm] = BIGF; hi[mm] = BIGF;   // up = BIG initially
    }
    if (tid == 0) { diag[0] = 0.0f; lo[0] = 0.0f; }   // origin diag R0[0][0]=0
    float up[4] = {BIGF, BIGF, BIGF, BIGF};

    float res = 0.f;

    for (int B = 0; B < STEPS; B += 8) {
        #pragma unroll
        for (int u = 0; u < 8; ++u) {
            float vn[4];
            #pragma unroll
            for (int mm = 0; mm < 4; ++mm) {
                float d = dring[u][mm];
                dring[u][mm] = dp[mm * 128];           // prefetch step s+8

                float m  = fminf(lo[mm], v[mm]);
                float x  = fmaxf(lo[mm], v[mm]);
                float e1 = ex2f(m - x);
                float e2 = ex2f(m - hi[mm]);
                vn[mm]   = (d + m) - lg2f((e1 + e2) + 1.0f);
            }
            dp += 512;

            if (u == 6 && B == 1016) res = vn[3];      // s=1022: R[511][511]

            // producer: lane31 publishes its 4 rows' values for step s
            if (is31) sts_v4(myslot + (size_t)(B + u) * 4,
                             vn[0], vn[1], vn[2], vn[3]);

            // cross-lane up values for next step
            float sh0 = __shfl_up_sync(0xffffffffu, vn[0], 1);
            float sh1 = __shfl_up_sync(0xffffffffu, vn[1], 1);
            float sh2 = __shfl_up_sync(0xffffffffu, vn[2], 1);
            float sh3 = __shfl_up_sync(0xffffffffu, vn[3], 1);

            // predecessor warp's step-s values (for our step s+1)
            const float* ps = prdslot + (size_t)(B + u) * 4;
            spin_lds(ps + 3);
            float4 L = *(const float4*)ps;
            float s0 = w0 ? BIGF : L.x;
            float s1 = w0 ? L.x  : L.y;
            float s2 = w0 ? L.y  : L.z;
            float s3 = w0 ? L.z  : L.w;

            float u0 = is0 ? s0 : sh0;
            float u1 = is0 ? s1 : sh1;
            float u2 = is0 ? s2 : sh2;
            float u3 = is0 ? s3 : sh3;

            // roll state: diag <- old up; lo/hi from (diag, up) off-chain
            diag[0] = up[0]; diag[1] = up[1]; diag[2] = up[2]; diag[3] = up[3];
            up[0] = u0; up[1] = u1; up[2] = u2; up[3] = u3;
            #pragma unroll
            for (int mm = 0; mm < 4; ++mm) {
                lo[mm] = fminf(diag[mm], up[mm]);
                hi[mm] = fmaxf(diag[mm], up[mm]);
                v[mm]  = vn[mm];
            }
        }
    }

    if (tid == 127)
        out[b] = res * 0.69314718055994531f;   // log2 -> natural domain
}

extern "C" void kernel_launch(void* const* d_in, const int* in_sizes, int n_in,
                              void* d_out, int out_size)
{
    (void)in_sizes; (void)n_in; (void)out_size;
    const float* X = (const float*)d_in[0];
    const float* Y = (const float*)d_in[1];
    float* out = (float*)d_out;

    static int smem_set = 0;
    const int smem_bytes = 4 * SLOTS * 4 * sizeof(float);   // 64 KB
    if (!smem_set) {
        cudaFuncSetAttribute(sdtw_kernel,
                             cudaFuncAttributeMaxDynamicSharedMemorySize,
                             smem_bytes);
        smem_set = 1;
    }

    dim3 g1(NM / 64, NM / 64, BATCH);
    pairdist_kernel<<<g1, 256>>>(X, Y);
    sdtw_kernel<<<BATCH, 128, smem_bytes>>>(out);
}

// round 9
// speedup vs baseline: 1.8868x; 1.8868x over previous
#include <cuda_runtime.h>
#include <cuda_bf16.h>
#include <cstdint>

#define NM     512
#define BATCH  32
#define DIMK   64
#define BIGF   1e30f
#define SENTU  0x7fc00000u

// Packed D (pre-scaled by log2 e): g_Dq[b][W][u][k] as float2.
// W = warp row-group (rows 64W+2k, 64W+2k+1), u = local step, col j = u-2k.
// UROWS = 592 (576 used + prefetch pad). Unwritten slots stay zero (BSS).
#define UROWS 592
__device__ __align__(16) float g_Dq[(size_t)BATCH * 8 * UROWS * 64];

// smem boundary rings: ring[r] written by warp r-1 (slot u = its step u,
// value = v1 of lane31 = row 64r-1, col u-62), read by warp r.
// ring0 has no producer -> all BIG. Slots >=576 never written -> preinit BIG.
#define RING 656

__device__ __forceinline__ float ex2f(float x) {
    float r; asm("ex2.approx.f32 %0, %1;" : "=f"(r) : "f"(x)); return r;
}
__device__ __forceinline__ float lg2f(float x) {
    float r; asm("lg2.approx.f32 %0, %1;" : "=f"(r) : "f"(x)); return r;
}
// smem spin (raw backward branch, no BSSY): wait until *p != sentinel.
__device__ __forceinline__ float spinv(const float* p) {
    unsigned a = (unsigned)__cvta_generic_to_shared(p);
    unsigned v;
    asm volatile(
        "{\n\t.reg .pred sp;\n"
        "SPINS%=:\n\t"
        "ld.volatile.shared.b32 %0, [%1];\n\t"
        "setp.eq.u32 sp, %0, 0x7fc00000;\n\t"
        "@sp bra SPINS%=;\n\t}"
        : "=r"(v) : "r"(a) : "memory");
    return __uint_as_float(v);
}
__device__ __forceinline__ void sts_vol(float* p, float v) {
    unsigned a = (unsigned)__cvta_generic_to_shared(p);
    asm volatile("st.volatile.shared.b32 [%0], %1;" :: "r"(a), "f"(v) : "memory");
}

// ---------------------------------------------------------------------------
// Kernel 1: pairwise sqdist * log2(e) packed into g_Dq.
// 64x64 tiles (i-tile == warp row-group W), 256 threads, 4x4 microtiles.
// ---------------------------------------------------------------------------
__global__ void __launch_bounds__(256) pairdist_kernel(
    const float* __restrict__ X, const float* __restrict__ Y)
{
    __shared__ __align__(16) float Xs[64 * 68];
    __shared__ __align__(16) float Ys[64 * 68];
    __shared__ __align__(16) float x2s[64];
    __shared__ __align__(16) float y2s[64];
    __shared__ __align__(16) float stage[64 * 66];   // stage[jl*66 + il]

    const int b  = blockIdx.z;
    const int i0 = blockIdx.x * 64;                  // W = blockIdx.x
    const int j0 = blockIdx.y * 64;
    const int tid = threadIdx.x;

    const float* Xb = X + ((size_t)b * NM + i0) * DIMK;
    const float* Yb = Y + ((size_t)b * NM + j0) * DIMK;

    for (int t = tid; t < 64 * 64; t += 256) {
        int r = t >> 6, k = t & 63;
        Xs[k * 68 + r] = Xb[r * DIMK + k];
        Ys[k * 68 + r] = Yb[r * DIMK + k];
    }
    __syncthreads();

    if (tid < 128) {
        int r = tid & 63;
        const float* S = (tid < 64) ? Xs : Ys;
        float acc = 0.f;
        #pragma unroll 8
        for (int k = 0; k < 64; ++k) { float v = S[k * 68 + r]; acc += v * v; }
        if (tid < 64) x2s[r] = acc; else y2s[r] = acc;
    }
    __syncthreads();

    const int tx = tid & 15, ty = tid >> 4;
    float acc[4][4];
    #pragma unroll
    for (int a = 0; a < 4; ++a)
        #pragma unroll
        for (int c = 0; c < 4; ++c) acc[a][c] = 0.f;

    #pragma unroll 8
    for (int k = 0; k < 64; ++k) {
        float4 xv = *(const float4*)&Xs[k * 68 + 4 * tx];
        float4 yv = *(const float4*)&Ys[k * 68 + 4 * ty];
        float xr[4] = {xv.x, xv.y, xv.z, xv.w};
        float yr[4] = {yv.x, yv.y, yv.z, yv.w};
        #pragma unroll
        for (int jj = 0; jj < 4; ++jj)
            #pragma unroll
            for (int ii = 0; ii < 4; ++ii)
                acc[jj][ii] += yr[jj] * xr[ii];
    }

    const float L2E = 1.4426950408889634f;
    float4 x2v = *(const float4*)&x2s[4 * tx];
    float xr2[4] = {x2v.x, x2v.y, x2v.z, x2v.w};
    #pragma unroll
    for (int jj = 0; jj < 4; ++jj) {
        float y2 = y2s[4 * ty + jj];
        #pragma unroll
        for (int ii = 0; ii < 4; ++ii)
            stage[(4 * ty + jj) * 66 + 4 * tx + ii] =
                (xr2[ii] + y2 - 2.f * acc[jj][ii]) * L2E;
    }
    __syncthreads();

    // Packed writeout: local step row c = jl + 2k (c in [0,126)); lane = k.
    // g_Dq[b][W][j0+c][k] = {stage[jl][2k], stage[jl][2k+1]}, jl = c-2k.
    const int wk   = tid >> 5;
    const int lane = tid & 31;
    float2* gout = (float2*)g_Dq + ((size_t)(b * 8 + blockIdx.x) * UROWS + j0) * 32;
    for (int c = wk; c < 126; c += 8) {
        int jl = c - 2 * lane;
        if ((unsigned)jl < 64u) {
            float2 p = *(const float2*)&stage[jl * 66 + 2 * lane];
            gout[(size_t)c * 32 + lane] = p;
        }
    }
}

// ---------------------------------------------------------------------------
// Kernel 2: soft-DTW, skew-2 wavefront. 1 CTA/batch, 8 warps.
// Lane k of warp w owns rows 64w+2k, +1; local step u computes col j = u-2k.
// Neighbor values (up/diag) arrive 2-3 steps early via shfl / boundary ring
// -> completely off the softmin dependency chain.
// ---------------------------------------------------------------------------
__global__ void __launch_bounds__(256, 1) sdtw_kernel(float* __restrict__ out)
{
    __shared__ __align__(16) float rings[9][RING];

    const int b    = blockIdx.x;
    const int tid  = threadIdx.x;
    const int w    = tid >> 5;
    const int lane = tid & 31;
    const bool is31 = (lane == 31);

    for (int t = tid; t < 9 * RING; t += 256) {
        int r = t / RING, s = t % RING;
        bool sent = (r >= 1) && (s < 576);
        rings[0][t] = sent ? __uint_as_float(SENTU) : BIGF;   // flat fill
    }
    __syncthreads();

    // D prefetch ring (float2 per lane per step).
    const float2* dp0 = (const float2*)g_Dq + (size_t)(b * 8 + w) * UROWS * 32 + lane;
    float2 dring[8];
    #pragma unroll
    for (int p = 0; p < 8; ++p) dring[p] = dp0[p * 32];
    const float2* dp = dp0 + 8 * 32;

    const float* rring = rings[w];       // consumer ring (warp w reads ring w)
    float*       wring = rings[w + 1];   // producer ring

    // Prefill boundary pipeline: value(col u) lives at slot u+62.
    float diagNow = spinv(rring + 61);   // col -1
    float upNow   = spinv(rring + 62);   // col 0
    float upNext  = spinv(rring + 63);   // col 1
    if (lane != 0) { diagNow = BIGF; upNow = BIGF; upNext = BIGF; }
    if (w == 0 && lane == 0) diagNow = 0.0f;   // R[-1][-1] = 0 (origin)

    float bnd[8];
    {
        (void)spinv(rring + 71);
        float4 c0 = *(const float4*)(rring + 64);
        float4 c1 = *(const float4*)(rring + 68);
        bnd[0]=c0.x; bnd[1]=c0.y; bnd[2]=c0.z; bnd[3]=c0.w;
        bnd[4]=c1.x; bnd[5]=c1.y; bnd[6]=c1.z; bnd[7]=c1.w;
    }

    float lo0 = fminf(diagNow, upNow), hi0 = fmaxf(diagNow, upNow);
    float left0 = BIGF;
    float lo1 = BIGF, hi1 = BIGF;
    float res = 0.f;

    for (int B = 0; B < 576; B += 8) {
        #pragma unroll
        for (int x = 0; x < 8; ++x) {
            float2 d2 = dring[x];
            dring[x] = dp[x * 32];                     // prefetch step u+8

            // cell0: softmin(diag, up, left0); {lo0,hi0}={diag,up} precomputed
            float m0 = fminf(lo0, left0);
            float x0 = fmaxf(lo0, left0);
            float v0 = (d2.x + m0) - lg2f(ex2f(m0 - x0) + ex2f(m0 - hi0) + 1.0f);

            // cell1: softmin(left0_prev, v0, left1_prev); {lo1,hi1} precomputed
            float m1 = fminf(lo1, v0);
            float x1 = fmaxf(lo1, v0);
            float v1 = (d2.y + m1) - lg2f(ex2f(m1 - x1) + ex2f(m1 - hi1) + 1.0f);

            if (x == 5) { if (B == 568) res = v1; }    // u=573: col 511 of row 511

            if (is31) sts_vol(wring + (B + x), v1);    // publish row 64w+63

            float sh = __shfl_up_sync(0xffffffffu, v1, 1);
            float newv = (lane == 0) ? bnd[x] : sh;    // value(col u+2)

            if (x == 7) {                              // next boundary chunk
                (void)spinv(rring + B + 79);
                float4 c0 = *(const float4*)(rring + B + 72);
                float4 c1 = *(const float4*)(rring + B + 76);
                bnd[0]=c0.x; bnd[1]=c0.y; bnd[2]=c0.z; bnd[3]=c0.w;
                bnd[4]=c1.x; bnd[5]=c1.y; bnd[6]=c1.z; bnd[7]=c1.w;
            }

            // roll pipeline (all off the softmin chain)
            lo0 = fminf(upNow, upNext);                // diag(u+1)=col u, up(u+1)=col u+1
            hi0 = fmaxf(upNow, upNext);
            upNow = upNext; upNext = newv;
            lo1 = fminf(v0, v1); hi1 = fmaxf(v0, v1);
            left0 = v0;
        }
        dp += 8 * 32;
    }

    if (tid == 255)
        out[b] = res * 0.69314718055994531f;           // log2 -> natural domain
}

extern "C" void kernel_launch(void* const* d_in, const int* in_sizes, int n_in,
                              void* d_out, int out_size)
{
    (void)in_sizes; (void)n_in; (void)out_size;
    const float* X = (const float*)d_in[0];
    const float* Y = (const float*)d_in[1];
    float* out = (float*)d_out;

    dim3 g1(NM / 64, NM / 64, BATCH);
    pairdist_kernel<<<g1, 256>>>(X, Y);
    sdtw_kernel<<<BATCH, 256>>>(out);
}